// round 8
// baseline (speedup 1.0000x reference)
#include <cuda_runtime.h>
#include <cuda_bf16.h>
#include <cstdint>

#define BATCH 8
#define SEQ   2048
#define DIM   256
#define HEADS 8
#define BQ 64
#define BK 64
#define NTHR 256
#define NP (BATCH * (SEQ + 1) * DIM)
#define NE (BATCH * SEQ * DIM)

// ---- smem byte offsets ----
#define OFF_QH 0
#define OFF_QL 32768
#define OFF_KH 65536
#define OFF_KL 98304
#define OFF_EH 131072
#define OFF_EL 163840
#define OFF_PH 196608
#define OFF_PL 204800
#define OFF_RS 212992
#define SMEM_TOTAL (OFF_RS + 256)
// reuse after key loop:
#define OFF_YH OFF_QH
#define OFF_YL OFF_QL
#define OFF_WH OFF_KH
#define OFF_WL OFF_KL

// pre-split operands (bf16 bits as ushort)
__device__ __align__(16) unsigned short g_ph[NP];
__device__ __align__(16) unsigned short g_pl[NP];
__device__ __align__(16) unsigned short g_eh[NE];
__device__ __align__(16) unsigned short g_el[NE];
__device__ __align__(16) unsigned short g_Wh[DIM * DIM];
__device__ __align__(16) unsigned short g_Wl[DIM * DIM];

// ---- helpers ----
__device__ __forceinline__ uint32_t smem_u32(const void* p) {
    uint32_t a;
    asm("{ .reg .u64 t; cvta.to.shared.u64 t, %1; cvt.u32.u64 %0, t; }" : "=r"(a) : "l"(p));
    return a;
}
__device__ __forceinline__ void cp16(uint32_t dst, const void* src) {
    asm volatile("cp.async.cg.shared.global [%0], [%1], 16;" :: "r"(dst), "l"(src));
}
#define CP_COMMIT() asm volatile("cp.async.commit_group;" ::: "memory")
#define CP_WAIT0()  asm volatile("cp.async.wait_group 0;" ::: "memory")
#define CP_WAIT1()  asm volatile("cp.async.wait_group 1;" ::: "memory")

__device__ __forceinline__ void ldsm4(uint32_t addr, uint32_t& r0, uint32_t& r1, uint32_t& r2, uint32_t& r3) {
    asm volatile("ldmatrix.sync.aligned.m8n8.x4.shared.b16 {%0,%1,%2,%3}, [%4];"
                 : "=r"(r0), "=r"(r1), "=r"(r2), "=r"(r3) : "r"(addr));
}
__device__ __forceinline__ void ldsm4t(uint32_t addr, uint32_t& r0, uint32_t& r1, uint32_t& r2, uint32_t& r3) {
    asm volatile("ldmatrix.sync.aligned.m8n8.x4.trans.shared.b16 {%0,%1,%2,%3}, [%4];"
                 : "=r"(r0), "=r"(r1), "=r"(r2), "=r"(r3) : "r"(addr));
}
__device__ __forceinline__ void mma16816(float* c, uint32_t a0, uint32_t a1, uint32_t a2, uint32_t a3,
                                         uint32_t b0, uint32_t b1) {
    asm volatile("mma.sync.aligned.m16n8k16.row.col.f32.bf16.bf16.f32 "
                 "{%0,%1,%2,%3}, {%4,%5,%6,%7}, {%8,%9}, {%0,%1,%2,%3};"
                 : "+f"(c[0]), "+f"(c[1]), "+f"(c[2]), "+f"(c[3])
                 : "r"(a0), "r"(a1), "r"(a2), "r"(a3), "r"(b0), "r"(b1));
}
__device__ __forceinline__ void split2(float x0, float x1, unsigned& hp, unsigned& lp) {
    __nv_bfloat16 h0 = __float2bfloat16_rn(x0);
    __nv_bfloat16 h1 = __float2bfloat16_rn(x1);
    __nv_bfloat16 l0 = __float2bfloat16_rn(x0 - __bfloat162float(h0));
    __nv_bfloat16 l1 = __float2bfloat16_rn(x1 - __bfloat162float(h1));
    hp = (unsigned)__bfloat16_as_ushort(h0) | ((unsigned)__bfloat16_as_ushort(h1) << 16);
    lp = (unsigned)__bfloat16_as_ushort(l0) | ((unsigned)__bfloat16_as_ushort(l1) << 16);
}
#define SWZ(row, colb) ((uint32_t)(colb) ^ (((uint32_t)(row) & 7u) << 4))

// ---------------------------------------------------------------------------
// Precompute: split p/e into hi/lo bf16 (vectorized x4)
// ---------------------------------------------------------------------------
__global__ void split_pe_kernel(const float4* __restrict__ p4, const float4* __restrict__ e4) {
    int i = blockIdx.x * blockDim.x + threadIdx.x;
    if (i < NP / 4) {
        float4 v = p4[i];
        unsigned h01, l01, h23, l23;
        split2(v.x, v.y, h01, l01);
        split2(v.z, v.w, h23, l23);
        *(uint2*)(g_ph + 4 * (size_t)i) = make_uint2(h01, h23);
        *(uint2*)(g_pl + 4 * (size_t)i) = make_uint2(l01, l23);
    }
    if (i < NE / 4) {
        float4 v = e4[i];
        unsigned h01, l01, h23, l23;
        split2(v.x, v.y, h01, l01);
        split2(v.z, v.w, h23, l23);
        *(uint2*)(g_eh + 4 * (size_t)i) = make_uint2(h01, h23);
        *(uint2*)(g_el + 4 * (size_t)i) = make_uint2(l01, l23);
    }
}

// W_eff[n][k] = sum_h W_o[n, h*DIM + k], split
__global__ void weff_kernel(const float* __restrict__ Wo) {
    int t = blockIdx.x * blockDim.x + threadIdx.x;
    int dout = t >> 8, din = t & 255;
    float s = 0.f;
#pragma unroll
    for (int h = 0; h < HEADS; h++)
        s += Wo[(size_t)dout * (DIM * HEADS) + h * DIM + din];
    __nv_bfloat16 hh = __float2bfloat16_rn(s);
    g_Wh[t] = __bfloat16_as_ushort(hh);
    g_Wl[t] = __bfloat16_as_ushort(__float2bfloat16_rn(s - __bfloat162float(hh)));
}

// ---------------------------------------------------------------------------
// Fused attention + projection, mma.sync bf16x3, paired q-tiles.
// 256 threads = 8 warps as 2 m-warps (32 rows) x 4 n-warps. B-fragments are
// reused across the two 16-row m-blocks in registers (31% fewer LDSM bytes).
// ---------------------------------------------------------------------------
__global__ __launch_bounds__(NTHR, 1)
void attn_kernel(float* __restrict__ out) {
    extern __shared__ char smem[];
    const uint32_t sb = smem_u32(smem);
    const int tid  = threadIdx.x;
    const int lane = tid & 31;
    const int wid  = tid >> 5;
    const int mw   = wid & 1;      // 2 m-warps, 32 rows each
    const int nw   = wid >> 1;     // 4 n-warps
    const int b    = blockIdx.y;
    const unsigned short* ph = g_ph + (size_t)b * (SEQ + 1) * DIM;
    const unsigned short* pl = g_pl + (size_t)b * (SEQ + 1) * DIM;
    const unsigned short* eh = g_eh + (size_t)b * SEQ * DIM;
    const unsigned short* el = g_el + (size_t)b * SEQ * DIM;
    float* rowsum = (float*)(smem + OFF_RS);

    // per-m-block indices (m2 = 0,1 -> rows mw*32 + m2*16 ..)
    const int rowA  = mw * 32 + (lane >> 2);          // C-frag row, m2=0
    const int arA   = mw * 32 + (lane & 15);          // A-frag row, m2=0
    const int key   = nw * 16 + (lane & 7) + ((lane >> 4) << 3);
    const int ldr   = tid >> 2;       // loader row 0..63
    const int lds0  = tid & 3;        // loader segment base

    for (int pass = 0; pass < 2; pass++) {
        const int qt = pass ? (int)blockIdx.x : 31 - (int)blockIdx.x;
        const int q0 = qt * BQ;
        if (tid < BQ) rowsum[tid] = 0.f;

        // ---- prologue: Q + K(0) (group 1), E(0) (group 2) ----
        {
            const unsigned short* qh = ph + (size_t)(q0 + ldr + 1) * DIM;
            const unsigned short* ql = pl + (size_t)(q0 + ldr + 1) * DIM;
            const unsigned short* kh = ph + (size_t)ldr * DIM;
            const unsigned short* kl = pl + (size_t)ldr * DIM;
#pragma unroll
            for (int j = 0; j < 8; j++) {
                const int seg = lds0 + j * 4;
                const uint32_t off = (uint32_t)ldr * 512u + SWZ(ldr, seg * 16);
                cp16(sb + OFF_QH + off, qh + seg * 8);
                cp16(sb + OFF_QL + off, ql + seg * 8);
                cp16(sb + OFF_KH + off, kh + seg * 8);
                cp16(sb + OFF_KL + off, kl + seg * 8);
            }
            CP_COMMIT();
            const unsigned short* vh = eh + (size_t)ldr * DIM;
            const unsigned short* vl = el + (size_t)ldr * DIM;
#pragma unroll
            for (int j = 0; j < 8; j++) {
                const int seg = lds0 + j * 4;
                const uint32_t off = (uint32_t)ldr * 512u + SWZ(ldr, seg * 16);
                cp16(sb + OFF_EH + off, vh + seg * 8);
                cp16(sb + OFF_EL + off, vl + seg * 8);
            }
            CP_COMMIT();
        }
        CP_WAIT1();
        __syncthreads();

        float yacc[16][4];     // [m2*8 + grp2][4]
#pragma unroll
        for (int i = 0; i < 16; i++)
#pragma unroll
            for (int j = 0; j < 4; j++) yacc[i][j] = 0.f;
        float rs[2][2] = {{0.f, 0.f}, {0.f, 0.f}};

        // ---- key-tile loop (pipelined) ----
        for (int kt = 0; kt <= qt; kt++) {
            const int k0 = kt * BK;

            // S GEMM: warp tile 32 rows x 16 keys (2 m-blocks share B frags)
            float sacc[2][2][4];
#pragma unroll
            for (int m2 = 0; m2 < 2; m2++)
#pragma unroll
                for (int i = 0; i < 2; i++)
#pragma unroll
                    for (int j = 0; j < 4; j++) sacc[m2][i][j] = 0.f;
#pragma unroll
            for (int ks = 0; ks < 16; ks++) {
                const uint32_t acb = (uint32_t)(ks * 32 + ((lane >> 4) << 4));
                const uint32_t kb  = (uint32_t)(ks * 32 + (((lane >> 3) & 1) << 4));
                const uint32_t koff = (uint32_t)key * 512u + SWZ(key, kb);
                uint32_t kh0, kh1, kh2, kh3, kl0, kl1, kl2, kl3;
                ldsm4(sb + OFF_KH + koff, kh0, kh1, kh2, kh3);
                ldsm4(sb + OFF_KL + koff, kl0, kl1, kl2, kl3);
#pragma unroll
                for (int m2 = 0; m2 < 2; m2++) {
                    const int ar = arA + m2 * 16;
                    const uint32_t aoff = (uint32_t)ar * 512u + SWZ(ar, acb);
                    uint32_t qh0, qh1, qh2, qh3, ql0, ql1, ql2, ql3;
                    ldsm4(sb + OFF_QH + aoff, qh0, qh1, qh2, qh3);
                    ldsm4(sb + OFF_QL + aoff, ql0, ql1, ql2, ql3);
                    mma16816(sacc[m2][0], qh0, qh1, qh2, qh3, kh0, kh1);
                    mma16816(sacc[m2][0], qh0, qh1, qh2, qh3, kl0, kl1);
                    mma16816(sacc[m2][0], ql0, ql1, ql2, ql3, kh0, kh1);
                    mma16816(sacc[m2][1], qh0, qh1, qh2, qh3, kh2, kh3);
                    mma16816(sacc[m2][1], qh0, qh1, qh2, qh3, kl2, kl3);
                    mma16816(sacc[m2][1], ql0, ql1, ql2, ql3, kh2, kh3);
                }
            }
            __syncthreads();     // all warps done reading K(kt)

            // prefetch K(kt+1) (overlaps epilogue + AV)
            if (kt < qt) {
                const unsigned short* kh = ph + (size_t)(k0 + BK + ldr) * DIM;
                const unsigned short* kl = pl + (size_t)(k0 + BK + ldr) * DIM;
#pragma unroll
                for (int j = 0; j < 8; j++) {
                    const int seg = lds0 + j * 4;
                    const uint32_t off = (uint32_t)ldr * 512u + SWZ(ldr, seg * 16);
                    cp16(sb + OFF_KH + off, kh + seg * 8);
                    cp16(sb + OFF_KL + off, kl + seg * 8);
                }
            }
            CP_COMMIT();

            // epilogue: scale/clip/mask/exp; rowsum partials; P -> smem
#pragma unroll
            for (int m2 = 0; m2 < 2; m2++) {
                const int r0 = rowA + m2 * 16;
                const int qg0 = q0 + r0, qg1 = qg0 + 8;
#pragma unroll
                for (int nt = 0; nt < 2; nt++) {
                    const int colL = nw * 16 + nt * 8 + (lane & 3) * 2;
                    const int kgl = k0 + colL;
                    float s00 = fminf(10.f, fmaxf(-10.f, sacc[m2][nt][0] * 0.0625f));
                    float s01 = fminf(10.f, fmaxf(-10.f, sacc[m2][nt][1] * 0.0625f));
                    float s10 = fminf(10.f, fmaxf(-10.f, sacc[m2][nt][2] * 0.0625f));
                    float s11 = fminf(10.f, fmaxf(-10.f, sacc[m2][nt][3] * 0.0625f));
                    float w00 = (kgl     <= qg0) ? __expf(s00) : 0.f;
                    float w01 = (kgl + 1 <= qg0) ? __expf(s01) : 0.f;
                    float w10 = (kgl     <= qg1) ? __expf(s10) : 0.f;
                    float w11 = (kgl + 1 <= qg1) ? __expf(s11) : 0.f;
                    rs[m2][0] += w00 + w01;
                    rs[m2][1] += w10 + w11;
                    unsigned h, l;
                    uint32_t o0 = (uint32_t)r0 * 128u + SWZ(r0, colL * 2);
                    split2(w00, w01, h, l);
                    *(uint32_t*)(smem + OFF_PH + o0) = h;
                    *(uint32_t*)(smem + OFF_PL + o0) = l;
                    uint32_t o1 = (uint32_t)(r0 + 8) * 128u + SWZ(r0 + 8, colL * 2);
                    split2(w10, w11, h, l);
                    *(uint32_t*)(smem + OFF_PH + o1) = h;
                    *(uint32_t*)(smem + OFF_PL + o1) = l;
                }
            }
            CP_WAIT1();          // E(kt) complete
            __syncthreads();     // P + E visible

            // AV GEMM: warp tile 32 rows x 64 dims (E frags shared across m2)
#pragma unroll
            for (int ks = 0; ks < 4; ks++) {
                const uint32_t acb = (uint32_t)(ks * 32 + ((lane >> 4) << 4));
                uint32_t pf[2][8];
#pragma unroll
                for (int m2 = 0; m2 < 2; m2++) {
                    const int ar = arA + m2 * 16;
                    const uint32_t aoff = (uint32_t)ar * 128u + SWZ(ar, acb);
                    ldsm4(sb + OFF_PH + aoff, pf[m2][0], pf[m2][1], pf[m2][2], pf[m2][3]);
                    ldsm4(sb + OFF_PL + aoff, pf[m2][4], pf[m2][5], pf[m2][6], pf[m2][7]);
                }
                const int key2 = ks * 16 + (lane & 15);
#pragma unroll
                for (int grp = 0; grp < 4; grp++) {
                    const uint32_t dcb = (uint32_t)((nw * 64 + grp * 16 + ((lane >> 4) << 3)) * 2);
                    const uint32_t eoff = (uint32_t)key2 * 512u + SWZ(key2, dcb);
                    uint32_t eh0, eh1, eh2, eh3, el0, el1, el2, el3;
                    ldsm4t(sb + OFF_EH + eoff, eh0, eh1, eh2, eh3);
                    ldsm4t(sb + OFF_EL + eoff, el0, el1, el2, el3);
#pragma unroll
                    for (int m2 = 0; m2 < 2; m2++) {
                        float* y0 = yacc[m2 * 8 + 2 * grp];
                        float* y1 = yacc[m2 * 8 + 2 * grp + 1];
                        mma16816(y0, pf[m2][0], pf[m2][1], pf[m2][2], pf[m2][3], eh0, eh1);
                        mma16816(y0, pf[m2][0], pf[m2][1], pf[m2][2], pf[m2][3], el0, el1);
                        mma16816(y0, pf[m2][4], pf[m2][5], pf[m2][6], pf[m2][7], eh0, eh1);
                        mma16816(y1, pf[m2][0], pf[m2][1], pf[m2][2], pf[m2][3], eh2, eh3);
                        mma16816(y1, pf[m2][0], pf[m2][1], pf[m2][2], pf[m2][3], el2, el3);
                        mma16816(y1, pf[m2][4], pf[m2][5], pf[m2][6], pf[m2][7], eh2, eh3);
                    }
                }
            }
            __syncthreads();     // all warps done reading E(kt)

            // prefetch E(kt+1)
            if (kt < qt) {
                const unsigned short* vh = eh + (size_t)(k0 + BK + ldr) * DIM;
                const unsigned short* vl = el + (size_t)(k0 + BK + ldr) * DIM;
#pragma unroll
                for (int j = 0; j < 8; j++) {
                    const int seg = lds0 + j * 4;
                    const uint32_t off = (uint32_t)ldr * 512u + SWZ(ldr, seg * 16);
                    cp16(sb + OFF_EH + off, vh + seg * 8);
                    cp16(sb + OFF_EL + off, vl + seg * 8);
                }
            }
            CP_COMMIT();
            CP_WAIT1();          // K(kt+1) complete
            __syncthreads();
        }

        // ---- rowsum reduce ----
#pragma unroll
        for (int m2 = 0; m2 < 2; m2++) {
            rs[m2][0] += __shfl_xor_sync(0xffffffffu, rs[m2][0], 1);
            rs[m2][0] += __shfl_xor_sync(0xffffffffu, rs[m2][0], 2);
            rs[m2][1] += __shfl_xor_sync(0xffffffffu, rs[m2][1], 1);
            rs[m2][1] += __shfl_xor_sync(0xffffffffu, rs[m2][1], 2);
            if ((lane & 3) == 0) {
                atomicAdd(&rowsum[rowA + m2 * 16], rs[m2][0]);
                atomicAdd(&rowsum[rowA + m2 * 16 + 8], rs[m2][1]);
            }
        }
        __syncthreads();

        // ---- normalize Y, split bf16 to smem (reuse Q area) ----
#pragma unroll
        for (int m2 = 0; m2 < 2; m2++) {
            const int r0 = rowA + m2 * 16;
            const int qg0 = q0 + r0, qg1 = qg0 + 8;
            const float sc0 = 1.f / (rowsum[r0] * (float)(qg0 + 1));
            const float sc1 = 1.f / (rowsum[r0 + 8] * (float)(qg1 + 1));
#pragma unroll
            for (int nt = 0; nt < 8; nt++) {
                const int col = nw * 64 + nt * 8 + (lane & 3) * 2;
                unsigned h, l;
                uint32_t o0 = (uint32_t)r0 * 512u + SWZ(r0, col * 2);
                split2(yacc[m2 * 8 + nt][0] * sc0, yacc[m2 * 8 + nt][1] * sc0, h, l);
                *(uint32_t*)(smem + OFF_YH + o0) = h;
                *(uint32_t*)(smem + OFF_YL + o0) = l;
                uint32_t o1 = (uint32_t)(r0 + 8) * 512u + SWZ(r0 + 8, col * 2);
                split2(yacc[m2 * 8 + nt][2] * sc1, yacc[m2 * 8 + nt][3] * sc1, h, l);
                *(uint32_t*)(smem + OFF_YH + o1) = h;
                *(uint32_t*)(smem + OFF_YL + o1) = l;
            }
        }

        // ---- projection: out[64,256] = Ynorm @ Weff^T, 4 K-chunks of 64 ----
        float pacc[16][4];
#pragma unroll
        for (int i = 0; i < 16; i++)
#pragma unroll
            for (int j = 0; j < 4; j++) pacc[i][j] = 0.f;

        for (int ch = 0; ch < 4; ch++) {
            __syncthreads();
            {   // each thread loads one dout row (hi + lo), 64 k-values = 8 segs
                const int dout = tid;
                const unsigned short* wh = g_Wh + (size_t)dout * 256 + ch * 64;
                const unsigned short* wl = g_Wl + (size_t)dout * 256 + ch * 64;
#pragma unroll
                for (int s = 0; s < 8; s++) {
                    const uint32_t off = (uint32_t)dout * 128u + SWZ(dout, s * 16);
                    cp16(sb + OFF_WH + off, wh + s * 8);
                    cp16(sb + OFF_WL + off, wl + s * 8);
                }
                CP_COMMIT();
                CP_WAIT0();
            }
            __syncthreads();

#pragma unroll
            for (int ks = 0; ks < 4; ks++) {
                const uint32_t acb = (uint32_t)(ch * 128 + ks * 32 + ((lane >> 4) << 4));
                uint32_t yf[2][8];
#pragma unroll
                for (int m2 = 0; m2 < 2; m2++) {
                    const int ar = arA + m2 * 16;
                    const uint32_t aoff = (uint32_t)ar * 512u + SWZ(ar, acb);
                    ldsm4(sb + OFF_YH + aoff, yf[m2][0], yf[m2][1], yf[m2][2], yf[m2][3]);
                    ldsm4(sb + OFF_YL + aoff, yf[m2][4], yf[m2][5], yf[m2][6], yf[m2][7]);
                }
#pragma unroll
                for (int pt = 0; pt < 4; pt++) {
                    const int dout2 = nw * 64 + pt * 16 + (lane & 7) + ((lane >> 4) << 3);
                    const uint32_t kb = (uint32_t)(ks * 32 + (((lane >> 3) & 1) << 4));
                    const uint32_t woff = (uint32_t)dout2 * 128u + SWZ(dout2, kb);
                    uint32_t wh0, wh1, wh2, wh3, wl0, wl1, wl2, wl3;
                    ldsm4(sb + OFF_WH + woff, wh0, wh1, wh2, wh3);
                    ldsm4(sb + OFF_WL + woff, wl0, wl1, wl2, wl3);
#pragma unroll
                    for (int m2 = 0; m2 < 2; m2++) {
                        float* c0 = pacc[m2 * 8 + 2 * pt];
                        float* c1 = pacc[m2 * 8 + 2 * pt + 1];
                        mma16816(c0, yf[m2][0], yf[m2][1], yf[m2][2], yf[m2][3], wh0, wh1);
                        mma16816(c0, yf[m2][0], yf[m2][1], yf[m2][2], yf[m2][3], wl0, wl1);
                        mma16816(c0, yf[m2][4], yf[m2][5], yf[m2][6], yf[m2][7], wh0, wh1);
                        mma16816(c1, yf[m2][0], yf[m2][1], yf[m2][2], yf[m2][3], wh2, wh3);
                        mma16816(c1, yf[m2][0], yf[m2][1], yf[m2][2], yf[m2][3], wl2, wl3);
                        mma16816(c1, yf[m2][4], yf[m2][5], yf[m2][6], yf[m2][7], wh2, wh3);
                    }
                }
            }
        }

        // ---- write output ----
        {
            float* ob = out + (size_t)b * SEQ * DIM;
#pragma unroll
            for (int m2 = 0; m2 < 2; m2++) {
                const int r0 = rowA + m2 * 16;
                const int qg0 = q0 + r0, qg1 = qg0 + 8;
#pragma unroll
                for (int nt = 0; nt < 8; nt++) {
                    const int col = nw * 64 + nt * 8 + (lane & 3) * 2;
                    *(float2*)(ob + (size_t)qg0 * DIM + col) = make_float2(pacc[m2 * 8 + nt][0], pacc[m2 * 8 + nt][1]);
                    *(float2*)(ob + (size_t)qg1 * DIM + col) = make_float2(pacc[m2 * 8 + nt][2], pacc[m2 * 8 + nt][3]);
                }
            }
        }
        __syncthreads();   // pass isolation (smem reuse)
    }
}

// ---------------------------------------------------------------------------
extern "C" void kernel_launch(void* const* d_in, const int* in_sizes, int n_in,
                              void* d_out, int out_size) {
    const float *e = nullptr, *p = nullptr, *wo = nullptr;
    for (int i = 0; i < n_in; i++) {
        if      (in_sizes[i] == NE)                e  = (const float*)d_in[i];
        else if (in_sizes[i] == NP)                p  = (const float*)d_in[i];
        else if (in_sizes[i] == DIM * DIM * HEADS) wo = (const float*)d_in[i];
    }

    cudaFuncSetAttribute(attn_kernel, cudaFuncAttributeMaxDynamicSharedMemorySize, SMEM_TOTAL);

    split_pe_kernel<<<(NP / 4 + 255) / 256, 256>>>((const float4*)p, (const float4*)e);
    weff_kernel<<<DIM * DIM / 256, 256>>>(wo);
    attn_kernel<<<dim3(16, BATCH), NTHR, SMEM_TOTAL>>>((float*)d_out);
}